// round 17
// baseline (speedup 1.0000x reference)
#include <cuda_runtime.h>
#include <cuda_bf16.h>
#include <math.h>
#include <stdint.h>

#define NN 50000
#define NE 800000
#define NG 64
#define NC 10
#define CAP 128   // per-node bucket: 4 replicas x 32 slots

__device__ __forceinline__ uint32_t f2tf32(float x) {
    uint32_t u;
    asm("cvt.rna.tf32.f32 %0, %1;" : "=r"(u) : "f"(x));
    return u;
}
__device__ __forceinline__ uint32_t pack_bf2(float a, float b) {
    __nv_bfloat162 p = __floats2bfloat162_rn(a, b);
    return *(uint32_t*)&p;
}
__device__ __forceinline__ float2 unpack_bf2(uint32_t u) {
    return __bfloat1622float2(*(__nv_bfloat162*)&u);
}

// ---------------- scratch ----------------------------------------------------
__device__ __align__(16) float g_dinv[NN];
__device__ int   g_cnt[NN];
__device__ int   g_cnt4[4 * NN];                            // replicated counters
__device__ __align__(16) unsigned short g_colb[NN * CAP];   // padded buckets
__device__ __align__(16) __nv_bfloat16 g_zx[NN * 8];
__device__ __align__(16) __nv_bfloat16 g_b16A[NN * 128];
__device__ __align__(16) __nv_bfloat16 g_b16B[NN * 128];
__device__ __align__(16) __nv_bfloat16 g_hO[NN * 256];
__device__ __align__(16) float g_Wt1[32 * 8];
__device__ __align__(16) float g_Wt2[64 * 32];
__device__ __align__(16) float g_Wt3[128 * 64];
__device__ __align__(16) float g_Wt4[256 * 128];
__device__ float g_pool[NG * 256];

// ---------------- preprocessing ---------------------------------------------
__global__ void init_kernel(const float* __restrict__ W1, const float* __restrict__ W2,
                            const float* __restrict__ W3, const float* __restrict__ W4) {
    int i = blockIdx.x * blockDim.x + threadIdx.x;
    if (i < NN) {
        g_cnt4[i] = 0;
        g_cnt4[NN + i] = 0;
        g_cnt4[2 * NN + i] = 0;
        g_cnt4[3 * NN + i] = 0;
    }
    if (i < NG * 256) g_pool[i] = 0.f;
    if (i < 32 * 8) {
        int n = i >> 3, k = i & 7;
        g_Wt1[i] = (k < 5) ? __uint_as_float(f2tf32(W1[k * 32 + n])) : 0.f;
    }
    if (i < 64 * 32) {
        int n = i >> 5, k = i & 31;
        g_Wt2[i] = __uint_as_float(f2tf32(W2[k * 64 + n]));
    }
    if (i < 128 * 64) {
        int n = i >> 6, k = i & 63;
        g_Wt3[i] = __uint_as_float(f2tf32(W3[k * 128 + n]));
    }
    if (i < 256 * 128) {
        int n = i >> 7, k = i & 127;
        g_Wt4[i] = __uint_as_float(f2tf32(W4[k * 256 + n]));
    }
}

// single edge pass, 4-way replicated counters (cuts same-address contention 4x)
__global__ void edges_kernel(const int* __restrict__ ei) {
    int e = blockIdx.x * blockDim.x + threadIdx.x;
    if (e >= NE) return;
    int s = ei[e];
    int d = ei[NE + e];
    int rep = e & 3;
    int pos = atomicAdd(&g_cnt4[rep * NN + d], 1);
    g_colb[d * CAP + rep * 32 + pos] = (unsigned short)s;
}

// compact 4 sub-buckets -> contiguous, total count, dinv, zx
__global__ void dinvzx_kernel(const float* __restrict__ x) {
    int i = blockIdx.x * blockDim.x + threadIdx.x;
    if (i >= NN) return;
    int c0 = g_cnt4[i], c1 = g_cnt4[NN + i];
    int c2 = g_cnt4[2 * NN + i], c3 = g_cnt4[3 * NN + i];
    unsigned short* b = g_colb + (size_t)i * CAP;
    int t = c0;
    for (int j = 0; j < c1; j++) b[t + j] = b[32 + j];
    t += c1;
    for (int j = 0; j < c2; j++) b[t + j] = b[64 + j];
    t += c2;
    for (int j = 0; j < c3; j++) b[t + j] = b[96 + j];
    t += c3;
    g_cnt[i] = t;
    float dv = rsqrtf((float)(t + 1));
    g_dinv[i] = dv;
    float v0 = x[(size_t)i * 5 + 0], v1 = x[(size_t)i * 5 + 1];
    float v2 = x[(size_t)i * 5 + 2], v3 = x[(size_t)i * 5 + 3];
    float v4 = x[(size_t)i * 5 + 4];
    uint4 pk;
    pk.x = pack_bf2(dv * v0, dv * v1);
    pk.y = pack_bf2(dv * v2, dv * v3);
    pk.z = pack_bf2(dv * v4, 0.f);
    pk.w = 0u;
    *(uint4*)(g_zx + (size_t)i * 8) = pk;
}

// ---------------- shared mma compute body ------------------------------------
template <int K, int NS, int NTOT, int SCALE>
__device__ __forceinline__ void mma_compute(
    const float* sA, const float* sB, int tid, int node0, int n0,
    const float* __restrict__ bias, __nv_bfloat16* __restrict__ out)
{
    constexpr int AS = K + 4;
    constexpr int KQ8 = K / 8;
    int warp = tid >> 5, lane = tid & 31;
    int g = lane >> 2, tg = lane & 3;
    int mrow = warp * 16;

    uint32_t a[KQ8][4];
    #pragma unroll
    for (int kk = 0; kk < KQ8; kk++) {
        const float* p0 = sA + (mrow + g) * AS + kk * 8 + tg;
        const float* p1 = sA + (mrow + g + 8) * AS + kk * 8 + tg;
        a[kk][0] = __float_as_uint(p0[0]);
        a[kk][1] = __float_as_uint(p1[0]);
        a[kk][2] = __float_as_uint(p0[4]);
        a[kk][3] = __float_as_uint(p1[4]);
    }

    int row0 = node0 + mrow + g;
    int row1 = row0 + 8;
    float sc0 = 1.f, sc1 = 1.f;
    if (SCALE) {
        if (row0 < NN) sc0 = __ldg(&g_dinv[row0]);
        if (row1 < NN) sc1 = __ldg(&g_dinv[row1]);
    }
    #pragma unroll 2
    for (int ng = 0; ng < NS / 8; ng++) {
        float d0 = 0.f, d1 = 0.f, d2 = 0.f, d3 = 0.f;
        const float* bp = sB + (ng * 8 + g) * AS + tg;
        #pragma unroll
        for (int kk = 0; kk < KQ8; kk++) {
            uint32_t b0 = __float_as_uint(bp[kk * 8]);
            uint32_t b1 = __float_as_uint(bp[kk * 8 + 4]);
            asm volatile(
                "mma.sync.aligned.m16n8k8.row.col.f32.tf32.tf32.f32 "
                "{%0,%1,%2,%3}, {%4,%5,%6,%7}, {%8,%9}, {%0,%1,%2,%3};"
                : "+f"(d0), "+f"(d1), "+f"(d2), "+f"(d3)
                : "r"(a[kk][0]), "r"(a[kk][1]), "r"(a[kk][2]), "r"(a[kk][3]),
                  "r"(b0), "r"(b1));
        }
        int col = n0 + ng * 8 + 2 * tg;
        float2 bs = __ldg((const float2*)&bias[col]);
        if (row0 < NN)
            *(uint32_t*)(out + (size_t)row0 * NTOT + col) =
                pack_bf2(fmaxf(d0 + bs.x, 0.f) * sc0, fmaxf(d1 + bs.y, 0.f) * sc0);
        if (row1 < NN)
            *(uint32_t*)(out + (size_t)row1 * NTOT + col) =
                pack_bf2(fmaxf(d2 + bs.x, 0.f) * sc1, fmaxf(d3 + bs.y, 0.f) * sc1);
    }
}

// ---------------- layer 1: fused agg(zx) + mma K=8, 512 threads -------------
__global__ __launch_bounds__(512) void mma1_kernel(
    const uint4* __restrict__ z, const float* __restrict__ Wt,
    const float* __restrict__ bias, __nv_bfloat16* __restrict__ out)
{
    constexpr int K = 8, AS = K + 4;
    extern __shared__ float smem[];
    float* sA = smem;
    float* sB = smem + 128 * AS;
    int tid = threadIdx.x;
    int node0 = blockIdx.x * 128;

    {
        int r = tid >> 2, h = tid & 3;
        int nd = node0 + r;
        float acc[8] = {0, 0, 0, 0, 0, 0, 0, 0};
        if (nd < NN) {
            int e0 = nd * CAP, end = e0 + g_cnt[nd];
            if (h == 0) {
                uint4 v = __ldg(&z[nd]);
                const uint32_t* u = (const uint32_t*)&v;
                #pragma unroll
                for (int j = 0; j < 4; j++) {
                    float2 fv = unpack_bf2(u[j]);
                    acc[2 * j] = fv.x; acc[2 * j + 1] = fv.y;
                }
            }
            for (int e = e0 + h; e < end; e += 4) {
                uint4 v0 = __ldg(&z[__ldg(&g_colb[e])]);
                const uint32_t* u0 = (const uint32_t*)&v0;
                #pragma unroll
                for (int j = 0; j < 4; j++) {
                    float2 f0 = unpack_bf2(u0[j]);
                    acc[2 * j] += f0.x; acc[2 * j + 1] += f0.y;
                }
            }
        }
        #pragma unroll
        for (int j = 0; j < 8; j++) {
            acc[j] += __shfl_down_sync(~0u, acc[j], 2);
            acc[j] += __shfl_down_sync(~0u, acc[j], 1);
        }
        if (h == 0) {
            float dv = (nd < NN) ? g_dinv[nd] : 0.f;
            float* dst = sA + r * AS;
            #pragma unroll
            for (int j = 0; j < 8; j++) dst[j] = dv * acc[j];
        }
    }
    if (tid < 64) {
        int r = tid >> 1, kq = tid & 1;
        float4 v = __ldg((const float4*)Wt + r * 2 + kq);
        *(float4*)(sB + r * AS + kq * 4) = v;
    }
    __syncthreads();
    if (tid < 256)
        mma_compute<8, 32, 32, 1>(sA, sB, tid, node0, 0, bias, out);
}

// ---------------- layer 2: fused agg(z1) + mma K=32, 512 threads ------------
__global__ __launch_bounds__(512) void mma2_kernel(
    const uint4* __restrict__ z, const float* __restrict__ Wt,
    const float* __restrict__ bias, __nv_bfloat16* __restrict__ out)
{
    constexpr int K = 32, AS = K + 4;
    extern __shared__ float smem[];
    float* sA = smem;
    float* sB = smem + 128 * AS;
    int tid = threadIdx.x;
    int node0 = blockIdx.x * 128;

    {
        int r = tid >> 2, c = tid & 3;
        int nd = node0 + r;
        float acc[8] = {0, 0, 0, 0, 0, 0, 0, 0};
        float dv = 0.f;
        if (nd < NN) {
            dv = g_dinv[nd];
            uint4 v = __ldg(&z[(size_t)nd * 4 + c]);
            const uint32_t* u = (const uint32_t*)&v;
            #pragma unroll
            for (int j = 0; j < 4; j++) {
                float2 fv = unpack_bf2(u[j]);
                acc[2 * j] = fv.x; acc[2 * j + 1] = fv.y;
            }
            int e = nd * CAP, end = e + g_cnt[nd];
            for (; e + 3 < end; e += 4) {
                int c0 = __ldg(&g_colb[e]),     c1 = __ldg(&g_colb[e + 1]);
                int c2 = __ldg(&g_colb[e + 2]), c3 = __ldg(&g_colb[e + 3]);
                uint4 v0 = __ldg(&z[(size_t)c0 * 4 + c]);
                uint4 v1 = __ldg(&z[(size_t)c1 * 4 + c]);
                uint4 v2 = __ldg(&z[(size_t)c2 * 4 + c]);
                uint4 v3 = __ldg(&z[(size_t)c3 * 4 + c]);
                const uint32_t* u0 = (const uint32_t*)&v0;
                const uint32_t* u1 = (const uint32_t*)&v1;
                const uint32_t* u2 = (const uint32_t*)&v2;
                const uint32_t* u3 = (const uint32_t*)&v3;
                #pragma unroll
                for (int j = 0; j < 4; j++) {
                    float2 f0 = unpack_bf2(u0[j]), f1 = unpack_bf2(u1[j]);
                    float2 f2 = unpack_bf2(u2[j]), f3 = unpack_bf2(u3[j]);
                    acc[2 * j]     += f0.x + f1.x + f2.x + f3.x;
                    acc[2 * j + 1] += f0.y + f1.y + f2.y + f3.y;
                }
            }
            for (; e < end; e++) {
                uint4 v0 = __ldg(&z[(size_t)__ldg(&g_colb[e]) * 4 + c]);
                const uint32_t* u0 = (const uint32_t*)&v0;
                #pragma unroll
                for (int j = 0; j < 4; j++) {
                    float2 f0 = unpack_bf2(u0[j]);
                    acc[2 * j] += f0.x; acc[2 * j + 1] += f0.y;
                }
            }
        }
        float* dst = sA + r * AS + c * 8;
        #pragma unroll
        for (int j = 0; j < 8; j++) dst[j] = dv * acc[j];
    }
    {
        int r = tid >> 3, kq = tid & 7;
        float4 v = __ldg((const float4*)Wt + (size_t)r * 8 + kq);
        *(float4*)(sB + r * AS + kq * 4) = v;
    }
    __syncthreads();
    if (tid < 256)
        mma_compute<32, 64, 64, 1>(sA, sB, tid, node0, 0, bias, out);
}

// ---------------- standalone agg (layers 3-4) --------------------------------
template <int F>
__global__ void aggb_kernel(const uint4* __restrict__ z, uint4* __restrict__ out) {
    constexpr int FQ8 = F / 8;
    int node = blockIdx.x * blockDim.y + threadIdx.y;
    if (node >= NN) return;
    int f = threadIdx.x;
    float acc[8];
    {
        uint4 v = __ldg(&z[(size_t)node * FQ8 + f]);
        const uint32_t* u = (const uint32_t*)&v;
        #pragma unroll
        for (int j = 0; j < 4; j++) {
            float2 fv = unpack_bf2(u[j]);
            acc[2 * j] = fv.x; acc[2 * j + 1] = fv.y;
        }
    }
    int e = node * CAP, end = e + g_cnt[node];
    for (; e + 3 < end; e += 4) {
        int c0 = __ldg(&g_colb[e]),     c1 = __ldg(&g_colb[e + 1]);
        int c2 = __ldg(&g_colb[e + 2]), c3 = __ldg(&g_colb[e + 3]);
        uint4 v0 = __ldg(&z[(size_t)c0 * FQ8 + f]);
        uint4 v1 = __ldg(&z[(size_t)c1 * FQ8 + f]);
        uint4 v2 = __ldg(&z[(size_t)c2 * FQ8 + f]);
        uint4 v3 = __ldg(&z[(size_t)c3 * FQ8 + f]);
        const uint32_t* u0 = (const uint32_t*)&v0;
        const uint32_t* u1 = (const uint32_t*)&v1;
        const uint32_t* u2 = (const uint32_t*)&v2;
        const uint32_t* u3 = (const uint32_t*)&v3;
        #pragma unroll
        for (int j = 0; j < 4; j++) {
            float2 f0 = unpack_bf2(u0[j]), f1 = unpack_bf2(u1[j]);
            float2 f2 = unpack_bf2(u2[j]), f3 = unpack_bf2(u3[j]);
            acc[2 * j]     += f0.x + f1.x + f2.x + f3.x;
            acc[2 * j + 1] += f0.y + f1.y + f2.y + f3.y;
        }
    }
    for (; e < end; e++) {
        uint4 v0 = __ldg(&z[(size_t)__ldg(&g_colb[e]) * FQ8 + f]);
        const uint32_t* u0 = (const uint32_t*)&v0;
        #pragma unroll
        for (int j = 0; j < 4; j++) {
            float2 f0 = unpack_bf2(u0[j]);
            acc[2 * j] += f0.x; acc[2 * j + 1] += f0.y;
        }
    }
    float dv = g_dinv[node];
    uint32_t pk[4];
    #pragma unroll
    for (int j = 0; j < 4; j++) pk[j] = pack_bf2(dv * acc[2 * j], dv * acc[2 * j + 1]);
    out[(size_t)node * FQ8 + f] = *(uint4*)pk;
}

// ---------------- layer 3 tiled mma (K=64, N=128) ----------------------------
__global__ __launch_bounds__(256) void mma3_kernel(
    const __nv_bfloat16* __restrict__ A, const float* __restrict__ Wt,
    const float* __restrict__ bias, __nv_bfloat16* __restrict__ out)
{
    constexpr int K = 64, NS = 128, AS = K + 4;
    constexpr int KQ = K / 4, KQ8 = K / 8;
    extern __shared__ float smem[];
    float* sA = smem;
    float* sB = smem + 128 * AS;
    int tid = threadIdx.x;
    int node0 = blockIdx.x * 128;

    const uint4* Ab = (const uint4*)A;
    for (int i = tid; i < 128 * KQ8; i += 256) {
        int r = i / KQ8, c = i - r * KQ8;
        int nd = node0 + r;
        uint4 v = make_uint4(0, 0, 0, 0);
        if (nd < NN) v = __ldg(&Ab[(size_t)nd * KQ8 + c]);
        const uint32_t* u = (const uint32_t*)&v;
        float* dst = sA + r * AS + c * 8;
        #pragma unroll
        for (int j = 0; j < 4; j++) {
            float2 fv = unpack_bf2(u[j]);
            dst[2 * j] = fv.x; dst[2 * j + 1] = fv.y;
        }
    }
    for (int i = tid; i < NS * KQ; i += 256) {
        int r = i / KQ, kq = i - r * KQ;
        float4 v = __ldg((const float4*)Wt + (size_t)r * KQ + kq);
        *(float4*)(sB + r * AS + kq * 4) = v;
    }
    __syncthreads();
    mma_compute<64, 128, 128, 1>(sA, sB, tid, node0, 0, bias, out);
}

// ---------------- persistent layer 4 mma (K=128, N=256) ----------------------
__global__ __launch_bounds__(256) void mma_l4_kernel(
    const __nv_bfloat16* __restrict__ A, const float* __restrict__ Wt,
    const float* __restrict__ bias, __nv_bfloat16* __restrict__ out)
{
    constexpr int K = 128, NS = 256, AS = K + 4;
    constexpr int KQ = K / 4, KQ8 = K / 8;
    constexpr int NTILES = (NN + 127) / 128;
    extern __shared__ float smem[];
    float* sA = smem;
    float* sB = smem + 128 * AS;
    int tid = threadIdx.x;

    for (int i = tid; i < NS * KQ; i += 256) {
        int r = i / KQ, kq = i - r * KQ;
        float4 v = __ldg((const float4*)Wt + (size_t)r * KQ + kq);
        *(float4*)(sB + r * AS + kq * 4) = v;
    }
    const uint4* Ab = (const uint4*)A;

    for (int tile = blockIdx.x; tile < NTILES; tile += gridDim.x) {
        int node0 = tile * 128;
        __syncthreads();
        for (int i = tid; i < 128 * KQ8; i += 256) {
            int r = i / KQ8, c = i - r * KQ8;
            int nd = node0 + r;
            uint4 v = make_uint4(0, 0, 0, 0);
            if (nd < NN) v = __ldg(&Ab[(size_t)nd * KQ8 + c]);
            const uint32_t* u = (const uint32_t*)&v;
            float* dst = sA + r * AS + c * 8;
            #pragma unroll
            for (int j = 0; j < 4; j++) {
                float2 fv = unpack_bf2(u[j]);
                dst[2 * j] = fv.x; dst[2 * j + 1] = fv.y;
            }
        }
        __syncthreads();
        mma_compute<128, 256, 256, 0>(sA, sB, tid, node0, 0, bias, out);
    }
}

// ---------------- mean-pool + head -------------------------------------------
__global__ void poolb_kernel(const __nv_bfloat16* __restrict__ h,
                             const int* __restrict__ batch) {
    const int CH = 64;
    int f = threadIdx.x;
    int n0 = blockIdx.x * CH;
    float acc = 0.f;
    int curg = -1;
    for (int i = 0; i < CH; i++) {
        int nd = n0 + i;
        if (nd >= NN) break;
        int g = batch[nd];
        if (g != curg) {
            if (curg >= 0) atomicAdd(&g_pool[curg * 256 + f], acc);
            acc = 0.f; curg = g;
        }
        acc += __bfloat162float(h[(size_t)nd * 256 + f]);
    }
    if (curg >= 0) atomicAdd(&g_pool[curg * 256 + f], acc);
}

__global__ void head_kernel(const int* __restrict__ bat,
                            const float* __restrict__ fcW, const float* __restrict__ fcb,
                            float* __restrict__ out) {
    __shared__ float slog[NG * NC];
    __shared__ float sinv[NG];
    int tid = threadIdx.x;
    if (tid < NG) {
        int g = tid;
        int lo = 0, hi = NN;
        while (lo < hi) { int m = (lo + hi) >> 1; if (bat[m] <= g) lo = m + 1; else hi = m; }
        int ubg = lo;
        lo = 0; hi = NN;
        while (lo < hi) { int m = (lo + hi) >> 1; if (bat[m] <= g - 1) lo = m + 1; else hi = m; }
        int cnt = ubg - lo;
        sinv[g] = 1.f / fmaxf((float)cnt, 1.f);
    }
    __syncthreads();
    if (tid < NG * NC) {
        int g = tid / NC, c = tid % NC;
        float inv = sinv[g];
        float a = fcb[c];
        for (int k = 0; k < 256; k++)
            a += g_pool[g * 256 + k] * inv * fcW[k * NC + c];
        slog[tid] = a;
    }
    __syncthreads();
    if (tid < NG * NC) {
        int g = tid / NC;
        float m = -1e30f;
        for (int i = 0; i < NC; i++) m = fmaxf(m, slog[g * NC + i]);
        float s = 0.f;
        for (int i = 0; i < NC; i++) s += expf(slog[g * NC + i] - m);
        out[tid] = slog[tid] - m - logf(s);
    }
}

// ---------------- launch -----------------------------------------------------
extern "C" void kernel_launch(void* const* d_in, const int* in_sizes, int n_in,
                              void* d_out, int out_size) {
    const float* x   = (const float*)d_in[0];
    const int*   ei  = (const int*)d_in[1];
    const int*   bat = (const int*)d_in[2];
    const float* W1 = (const float*)d_in[3];
    const float* b1 = (const float*)d_in[4];
    const float* W2 = (const float*)d_in[5];
    const float* b2 = (const float*)d_in[6];
    const float* W3 = (const float*)d_in[7];
    const float* b3 = (const float*)d_in[8];
    const float* W4 = (const float*)d_in[9];
    const float* b4 = (const float*)d_in[10];
    const float* fcW = (const float*)d_in[11];
    const float* fcb = (const float*)d_in[12];
    float* out = (float*)d_out;

    float *Wt1, *Wt2, *Wt3, *Wt4;
    __nv_bfloat16 *zx, *bA, *bB, *hO;
    cudaGetSymbolAddress((void**)&zx, g_zx);
    cudaGetSymbolAddress((void**)&bA, g_b16A);
    cudaGetSymbolAddress((void**)&bB, g_b16B);
    cudaGetSymbolAddress((void**)&hO, g_hO);
    cudaGetSymbolAddress((void**)&Wt1, g_Wt1);
    cudaGetSymbolAddress((void**)&Wt2, g_Wt2);
    cudaGetSymbolAddress((void**)&Wt3, g_Wt3);
    cudaGetSymbolAddress((void**)&Wt4, g_Wt4);

    const int sm1  = (128 * 12 + 32 * 12) * 4;
    const int sm2  = (128 * 36 + 64 * 36) * 4;
    const int smL3 = (128 * 68 + 128 * 68) * 4;
    const int smL4 = (128 * 132 + 256 * 132) * 4;
    cudaFuncSetAttribute(mma3_kernel,
                         cudaFuncAttributeMaxDynamicSharedMemorySize, smL3);
    cudaFuncSetAttribute(mma_l4_kernel,
                         cudaFuncAttributeMaxDynamicSharedMemorySize, smL4);

    const int NB = (NN + 255) / 256;
    const int EB = (NE + 255) / 256;

    init_kernel<<<NB, 256>>>(W1, W2, W3, W4);
    edges_kernel<<<EB, 256>>>(ei);
    dinvzx_kernel<<<NB, 256>>>(x);

    mma1_kernel<<<391, 512, sm1>>>((const uint4*)zx, Wt1, b1, bA);
    mma2_kernel<<<391, 512, sm2>>>((const uint4*)bA, Wt2, b2, bB);
    {
        dim3 blk(8, 32);
        aggb_kernel<64><<<(NN + 31) / 32, blk>>>((const uint4*)bB, (uint4*)bA);
        mma3_kernel<<<391, 256, smL3>>>(bA, Wt3, b3, bB);
    }
    {
        dim3 blk(16, 16);
        aggb_kernel<128><<<(NN + 15) / 16, blk>>>((const uint4*)bB, (uint4*)bA);
        mma_l4_kernel<<<148, 256, smL4>>>(bA, Wt4, b4, hO);
    }

    poolb_kernel<<<(NN + 63) / 64, 256>>>(hO, bat);
    head_kernel<<<1, 640>>>(bat, fcW, fcb, out);

    (void)in_sizes; (void)n_in; (void)out_size;
}